// round 16
// baseline (speedup 1.0000x reference)
#include <cuda_runtime.h>
#include <cuda_bf16.h>
#include <stdint.h>
#include <math.h>

// ---------------- problem constants ----------------
#define D_DIM 2048
#define M_DIM 7168
#define E_NUM 8
#define T_TOK 4096
#define TR    (T_TOK * 2)

#define TILE_M 128
#define CHUNK_M 1792
#define N_CHUNKS (M_DIM / CHUNK_M)          // 4
#define PADROWS  (TR + E_NUM * TILE_M)      // 9216
#define MAX_RT   80

#define BK 32
#define PITCH 80                            // smem row pitch = 20 banks (conflict-free)

// per-stage smem layout (bytes)
#define OFF_AH 0
#define OFF_AL 10240
#define G1_B1H 20480
#define G1_B1L 23040
#define G1_B3H 25600
#define G1_B3L 28160
#define G2_BH  20480
#define G2_BL  25600
#define STG_BYTES 30720
#define SMEM_TOTAL (2 * STG_BYTES)          // 61440

// ---------------- static device scratch (~167 MB total — proven-safe size) ----------------
__device__ __nv_bfloat16 g_xs[(size_t)T_TOK * 2 * D_DIM];       // x split [tok][part][k], 33.5 MB
__device__ __nv_bfloat16 g_hcs[(size_t)PADROWS * 2 * CHUNK_M];  // h split [row][part][k], 66 MB
__device__ float g_outrep[(size_t)TR * D_DIM];                  // 67 MB
__device__ int   g_row_map[PADROWS];
__device__ int   g_repl_map[PADROWS];
__device__ int   g_eidx[TR];
__device__ float g_tw[TR];
__device__ int   g_tile_e[MAX_RT];
__device__ int   g_tile_row[MAX_RT];
__device__ int   g_ntiles;

// ---------------- helpers ----------------
__device__ __forceinline__ uint32_t phi(float a, float b) {
    __nv_bfloat162 t = __floats2bfloat162_rn(a, b);
    return *reinterpret_cast<uint32_t*>(&t);
}
__device__ __forceinline__ uint32_t plo(float a, float b) {
    float ah = __bfloat162float(__float2bfloat16_rn(a));
    float bh = __bfloat162float(__float2bfloat16_rn(b));
    return phi(a - ah, b - bh);
}
__device__ __forceinline__ void mma16816(float* c, const uint32_t* a, const uint32_t* b) {
    asm volatile(
        "mma.sync.aligned.m16n8k16.row.col.f32.bf16.bf16.f32 "
        "{%0,%1,%2,%3}, {%4,%5,%6,%7}, {%8,%9}, {%0,%1,%2,%3};"
        : "+f"(c[0]), "+f"(c[1]), "+f"(c[2]), "+f"(c[3])
        : "r"(a[0]), "r"(a[1]), "r"(a[2]), "r"(a[3]), "r"(b[0]), "r"(b[1]));
}
__device__ __forceinline__ uint32_t lds32(const char* p) {
    return *reinterpret_cast<const uint32_t*>(p);
}
__device__ __forceinline__ float silu(float v) {
    return v / (1.f + __expf(-v));
}

// ---------------- init ----------------
__global__ void k_init() {
    for (int i = threadIdx.x; i < PADROWS; i += blockDim.x) {
        g_row_map[i]  = -1;
        g_repl_map[i] = -1;
    }
}

// ---------------- x split ----------------
__global__ void k_xsplit(const float* __restrict__ x) {
    size_t i = (size_t)blockIdx.x * blockDim.x + threadIdx.x;
    if (i >= (size_t)T_TOK * D_DIM) return;
    int tok = (int)(i / D_DIM), k = (int)(i % D_DIM);
    float v = x[i];
    __nv_bfloat16 h = __float2bfloat16_rn(v);
    g_xs[((size_t)tok * 2) * D_DIM + k] = h;
    g_xs[((size_t)tok * 2 + 1) * D_DIM + k] = __float2bfloat16_rn(v - __bfloat162float(h));
}

// ---------------- router ----------------
__global__ void k_router(const float* __restrict__ x, const float* __restrict__ gw) {
    int warp = (blockIdx.x * blockDim.x + threadIdx.x) >> 5;
    int lane = threadIdx.x & 31;
    if (warp >= T_TOK) return;
    const float* xr = x + (size_t)warp * D_DIM;
    float acc[8] = {0.f,0.f,0.f,0.f,0.f,0.f,0.f,0.f};
    for (int k = lane; k < D_DIM; k += 32) {
        float xv = xr[k];
        const float4* g4 = (const float4*)(gw + (size_t)k * E_NUM);
        float4 g0 = g4[0], g1 = g4[1];
        acc[0] += xv * g0.x; acc[1] += xv * g0.y; acc[2] += xv * g0.z; acc[3] += xv * g0.w;
        acc[4] += xv * g1.x; acc[5] += xv * g1.y; acc[6] += xv * g1.z; acc[7] += xv * g1.w;
    }
#pragma unroll
    for (int e = 0; e < 8; e++)
#pragma unroll
        for (int o = 16; o > 0; o >>= 1)
            acc[e] += __shfl_xor_sync(0xFFFFFFFFu, acc[e], o);
    if (lane == 0) {
        int e0 = 0; float l0 = acc[0];
#pragma unroll
        for (int e = 1; e < 8; e++) if (acc[e] > l0) { l0 = acc[e]; e0 = e; }
        int e1 = -1; float l1 = -3.4e38f;
#pragma unroll
        for (int e = 0; e < 8; e++) if (e != e0 && acc[e] > l1) { l1 = acc[e]; e1 = e; }
        float w0 = 1.f / (1.f + __expf(l1 - l0));
        g_eidx[2 * warp] = e0; g_eidx[2 * warp + 1] = e1;
        g_tw[2 * warp] = w0;   g_tw[2 * warp + 1] = 1.f - w0;
    }
}

// ---------------- permutation + tile list ----------------
__global__ void k_perm() {
    __shared__ int sc[E_NUM], soff[E_NUM], scur[E_NUM];
    int t = threadIdx.x;
    if (t < E_NUM) { sc[t] = 0; scur[t] = 0; }
    __syncthreads();
    for (int r = t; r < TR; r += blockDim.x) atomicAdd(&sc[g_eidx[r]], 1);
    __syncthreads();
    if (t == 0) {
        int off = 0, nt = 0;
        for (int e = 0; e < E_NUM; e++) {
            soff[e] = off;
            int cnt = sc[e];
            for (int t0 = 0; t0 < cnt; t0 += TILE_M) {
                g_tile_e[nt] = e; g_tile_row[nt] = off + t0; nt++;
            }
            off += ((cnt + TILE_M - 1) / TILE_M) * TILE_M;
        }
        g_ntiles = nt;
    }
    __syncthreads();
    for (int r = t; r < TR; r += blockDim.x) {
        int e = g_eidx[r];
        int pos = soff[e] + atomicAdd(&scur[e], 1);
        g_row_map[pos]  = r >> 1;
        g_repl_map[pos] = r;
    }
}

// ============ GEMM1: CTA 128m x 32n, warp 32m x 16n over W1 & W3 ============
__global__ void __launch_bounds__(256, 2)
k_gemm1(const float* __restrict__ w1, const float* __restrict__ w3, int c0) {
    extern __shared__ char smem[];
    int bx = blockIdx.x;
    if (bx >= g_ntiles) return;
    int e  = g_tile_e[bx];
    int r0 = g_tile_row[bx];
    int nl = blockIdx.y * 32;

    const float* W1 = w1 + (size_t)e * D_DIM * M_DIM + c0 + nl;
    const float* W3 = w3 + (size_t)e * D_DIM * M_DIM + c0 + nl;

    int tid = threadIdx.x;
    int w = tid >> 5, lane = tid & 31, g = lane >> 2, q = lane & 3;
    int m0 = (w & 3) * 32, n0w = (w >> 2) * 16;

    // A loader (pre-split bf16): thread -> (row, part); 64 B/stage via 4x LDG.128
    int arow = tid >> 1, apart = tid & 1;
    int gr = g_row_map[r0 + arow];
    const uint4* asrc = (const uint4*)(g_xs +
        ((size_t)((gr >= 0 ? gr : 0) * 2 + apart)) * D_DIM);
    uint32_t adoff = (apart ? OFF_AL : OFF_AH) + (uint32_t)arow * PITCH;

    // B loader (fp32 + convert, verified round-11 path)
    int bn = tid & 31, kg = tid >> 5;
    float2 vb1[2], vb3[2];

    char* buf[2] = { smem, smem + STG_BYTES };
    float c1[2][2][4] = {{{0}}}, c3[2][2][4] = {{{0}}};

    uint4 pa[4];
#pragma unroll
    for (int i = 0; i < 4; i++) pa[i] = asrc[i];
#pragma unroll
    for (int j = 0; j < 2; j++) {
        int kk = (kg * 2 + j) * 2;
        vb1[j] = make_float2(W1[(size_t)kk * M_DIM + bn], W1[(size_t)(kk + 1) * M_DIM + bn]);
        vb3[j] = make_float2(W3[(size_t)kk * M_DIM + bn], W3[(size_t)(kk + 1) * M_DIM + bn]);
    }
    {
        char* s = buf[0];
        *(uint4*)(s + adoff +  0) = pa[0];
        *(uint4*)(s + adoff + 16) = pa[1];
        *(uint4*)(s + adoff + 32) = pa[2];
        *(uint4*)(s + adoff + 48) = pa[3];
        uint32_t bo = (uint32_t)bn * PITCH + kg * 8;
        *(uint2*)(s + G1_B1H + bo) = make_uint2(phi(vb1[0].x, vb1[0].y), phi(vb1[1].x, vb1[1].y));
        *(uint2*)(s + G1_B1L + bo) = make_uint2(plo(vb1[0].x, vb1[0].y), plo(vb1[1].x, vb1[1].y));
        *(uint2*)(s + G1_B3H + bo) = make_uint2(phi(vb3[0].x, vb3[0].y), phi(vb3[1].x, vb3[1].y));
        *(uint2*)(s + G1_B3L + bo) = make_uint2(plo(vb3[0].x, vb3[0].y), plo(vb3[1].x, vb3[1].y));
    }
    __syncthreads();

    const int NIT = D_DIM / BK;   // 64
    for (int it = 0; it < NIT; it++) {
        bool pf = (it + 1 < NIT);
        if (pf) {
            int sbase = (it + 1) * 4;
#pragma unroll
            for (int i = 0; i < 4; i++) pa[i] = asrc[sbase + i];
            int nk0 = (it + 1) * BK;
#pragma unroll
            for (int j = 0; j < 2; j++) {
                int kk = nk0 + (kg * 2 + j) * 2;
                vb1[j] = make_float2(W1[(size_t)kk * M_DIM + bn], W1[(size_t)(kk + 1) * M_DIM + bn]);
                vb3[j] = make_float2(W3[(size_t)kk * M_DIM + bn], W3[(size_t)(kk + 1) * M_DIM + bn]);
            }
        }
        {
            const char* s = buf[it & 1];
#pragma unroll
            for (int ks = 0; ks < 2; ks++) {
                uint32_t aH[2][4], aL[2][4];
#pragma unroll
                for (int mi = 0; mi < 2; mi++) {
                    uint32_t o = (uint32_t)(m0 + mi * 16 + g) * PITCH + ks * 32 + q * 4;
                    aH[mi][0] = lds32(s + OFF_AH + o);
                    aH[mi][1] = lds32(s + OFF_AH + o + 8 * PITCH);
                    aH[mi][2] = lds32(s + OFF_AH + o + 16);
                    aH[mi][3] = lds32(s + OFF_AH + o + 8 * PITCH + 16);
                    aL[mi][0] = lds32(s + OFF_AL + o);
                    aL[mi][1] = lds32(s + OFF_AL + o + 8 * PITCH);
                    aL[mi][2] = lds32(s + OFF_AL + o + 16);
                    aL[mi][3] = lds32(s + OFF_AL + o + 8 * PITCH + 16);
                }
                uint32_t bh[2][2], bl[2][2];
#pragma unroll
                for (int ni = 0; ni < 2; ni++) {
                    uint32_t o = (uint32_t)(n0w + ni * 8 + g) * PITCH + ks * 32 + q * 4;
                    bh[ni][0] = lds32(s + G1_B1H + o);
                    bh[ni][1] = lds32(s + G1_B1H + o + 16);
                    bl[ni][0] = lds32(s + G1_B1L + o);
                    bl[ni][1] = lds32(s + G1_B1L + o + 16);
                }
#pragma unroll
                for (int mi = 0; mi < 2; mi++)
#pragma unroll
                    for (int ni = 0; ni < 2; ni++) {
                        mma16816(c1[mi][ni], aH[mi], bh[ni]);
                        mma16816(c1[mi][ni], aL[mi], bh[ni]);
                        mma16816(c1[mi][ni], aH[mi], bl[ni]);
                    }
#pragma unroll
                for (int ni = 0; ni < 2; ni++) {
                    uint32_t o = (uint32_t)(n0w + ni * 8 + g) * PITCH + ks * 32 + q * 4;
                    bh[ni][0] = lds32(s + G1_B3H + o);
                    bh[ni][1] = lds32(s + G1_B3H + o + 16);
                    bl[ni][0] = lds32(s + G1_B3L + o);
                    bl[ni][1] = lds32(s + G1_B3L + o + 16);
                }
#pragma unroll
                for (int mi = 0; mi < 2; mi++)
#pragma unroll
                    for (int ni = 0; ni < 2; ni++) {
                        mma16816(c3[mi][ni], aH[mi], bh[ni]);
                        mma16816(c3[mi][ni], aL[mi], bh[ni]);
                        mma16816(c3[mi][ni], aH[mi], bl[ni]);
                    }
            }
        }
        if (pf) {
            char* s = buf[(it + 1) & 1];
            *(uint4*)(s + adoff +  0) = pa[0];
            *(uint4*)(s + adoff + 16) = pa[1];
            *(uint4*)(s + adoff + 32) = pa[2];
            *(uint4*)(s + adoff + 48) = pa[3];
            uint32_t bo = (uint32_t)bn * PITCH + kg * 8;
            *(uint2*)(s + G1_B1H + bo) = make_uint2(phi(vb1[0].x, vb1[0].y), phi(vb1[1].x, vb1[1].y));
            *(uint2*)(s + G1_B1L + bo) = make_uint2(plo(vb1[0].x, vb1[0].y), plo(vb1[1].x, vb1[1].y));
            *(uint2*)(s + G1_B3H + bo) = make_uint2(phi(vb3[0].x, vb3[0].y), phi(vb3[1].x, vb3[1].y));
            *(uint2*)(s + G1_B3L + bo) = make_uint2(plo(vb3[0].x, vb3[0].y), plo(vb3[1].x, vb3[1].y));
        }
        __syncthreads();
    }

    // epilogue: h split bf16 -> g_hcs
#pragma unroll
    for (int mi = 0; mi < 2; mi++)
#pragma unroll
        for (int ni = 0; ni < 2; ni++) {
            int rt = m0 + mi * 16 + g;
            int cb = nl + n0w + ni * 8 + q * 2;
            float h0 = silu(c1[mi][ni][0]) * c3[mi][ni][0];
            float h1 = silu(c1[mi][ni][1]) * c3[mi][ni][1];
            size_t b0 = ((size_t)(r0 + rt) * 2) * CHUNK_M + cb;
            *(uint32_t*)&g_hcs[b0]           = phi(h0, h1);
            *(uint32_t*)&g_hcs[b0 + CHUNK_M] = plo(h0, h1);
            float h2 = silu(c1[mi][ni][2]) * c3[mi][ni][2];
            float h3 = silu(c1[mi][ni][3]) * c3[mi][ni][3];
            size_t b1 = ((size_t)(r0 + rt + 8) * 2) * CHUNK_M + cb;
            *(uint32_t*)&g_hcs[b1]           = phi(h2, h3);
            *(uint32_t*)&g_hcs[b1 + CHUNK_M] = plo(h2, h3);
        }
}

// ============ GEMM2: CTA 128m x 64n, warp 32m x 32n ============
__global__ void __launch_bounds__(256, 2)
k_gemm2(const float* __restrict__ w2, int c0, int first) {
    extern __shared__ char smem[];
    int bx = blockIdx.x;
    if (bx >= g_ntiles) return;
    int e  = g_tile_e[bx];
    int r0 = g_tile_row[bx];
    int n0 = blockIdx.y * 64;

    const float* W2 = w2 + (size_t)e * M_DIM * D_DIM + (size_t)c0 * D_DIM + n0;

    int tid = threadIdx.x;
    int w = tid >> 5, lane = tid & 31, g = lane >> 2, q = lane & 3;
    int m0 = (w & 3) * 32, n0w = (w >> 2) * 32;

    // A loader (pre-split bf16 h)
    int arow = tid >> 1, apart = tid & 1;
    const uint4* asrc = (const uint4*)(g_hcs +
        ((size_t)(r0 + arow) * 2 + apart) * CHUNK_M);
    uint32_t adoff = (apart ? OFF_AL : OFF_AH) + (uint32_t)arow * PITCH;

    // B loader (fp32 + convert, verified round-11 path)
    int bn = tid & 63, kg = tid >> 6;
    float2 vb[4];

    char* buf[2] = { smem, smem + STG_BYTES };
    float c[2][4][4] = {{{0}}};

    uint4 pa[4];
#pragma unroll
    for (int i = 0; i < 4; i++) pa[i] = asrc[i];
#pragma unroll
    for (int j = 0; j < 4; j++) {
        int kk = (kg * 4 + j) * 2;
        vb[j] = make_float2(W2[(size_t)kk * D_DIM + bn], W2[(size_t)(kk + 1) * D_DIM + bn]);
    }
    {
        char* s = buf[0];
        *(uint4*)(s + adoff +  0) = pa[0];
        *(uint4*)(s + adoff + 16) = pa[1];
        *(uint4*)(s + adoff + 32) = pa[2];
        *(uint4*)(s + adoff + 48) = pa[3];
        uint32_t bo = (uint32_t)bn * PITCH + kg * 16;
        *(uint4*)(s + G2_BH + bo) = make_uint4(phi(vb[0].x, vb[0].y), phi(vb[1].x, vb[1].y),
                                               phi(vb[2].x, vb[2].y), phi(vb[3].x, vb[3].y));
        *(uint4*)(s + G2_BL + bo) = make_uint4(plo(vb[0].x, vb[0].y), plo(vb[1].x, vb[1].y),
                                               plo(vb[2].x, vb[2].y), plo(vb[3].x, vb[3].y));
    }
    __syncthreads();

    const int NIT = CHUNK_M / BK;  // 56
    for (int it = 0; it < NIT; it++) {
        bool pf = (it + 1 < NIT);
        if (pf) {
            int sbase = (it + 1) * 4;
#pragma unroll
            for (int i = 0; i < 4; i++) pa[i] = asrc[sbase + i];
            int nk0 = (it + 1) * BK;
#pragma unroll
            for (int j = 0; j < 4; j++) {
                int kk = nk0 + (kg * 4 + j) * 2;
                vb[j] = make_float2(W2[(size_t)kk * D_DIM + bn], W2[(size_t)(kk + 1) * D_DIM + bn]);
            }
        }
        {
            const char* s = buf[it & 1];
#pragma unroll
            for (int ks = 0; ks < 2; ks++) {
                uint32_t aH[2][4], aL[2][4];
#pragma unroll
                for (int mi = 0; mi < 2; mi++) {
                    uint32_t o = (uint32_t)(m0 + mi * 16 + g) * PITCH + ks * 32 + q * 4;
                    aH[mi][0] = lds32(s + OFF_AH + o);
                    aH[mi][1] = lds32(s + OFF_AH + o + 8 * PITCH);
                    aH[mi][2] = lds32(s + OFF_AH + o + 16);
                    aH[mi][3] = lds32(s + OFF_AH + o + 8 * PITCH + 16);
                    aL[mi][0] = lds32(s + OFF_AL + o);
                    aL[mi][1] = lds32(s + OFF_AL + o + 8 * PITCH);
                    aL[mi][2] = lds32(s + OFF_AL + o + 16);
                    aL[mi][3] = lds32(s + OFF_AL + o + 8 * PITCH + 16);
                }
#pragma unroll
                for (int ni = 0; ni < 4; ni++) {
                    uint32_t o = (uint32_t)(n0w + ni * 8 + g) * PITCH + ks * 32 + q * 4;
                    uint32_t bHf[2], bLf[2];
                    bHf[0] = lds32(s + G2_BH + o);
                    bHf[1] = lds32(s + G2_BH + o + 16);
                    bLf[0] = lds32(s + G2_BL + o);
                    bLf[1] = lds32(s + G2_BL + o + 16);
#pragma unroll
                    for (int mi = 0; mi < 2; mi++) {
                        mma16816(c[mi][ni], aH[mi], bHf);
                        mma16816(c[mi][ni], aL[mi], bHf);
                        mma16816(c[mi][ni], aH[mi], bLf);
                    }
                }
            }
        }
        if (pf) {
            char* s = buf[(it + 1) & 1];
            *(uint4*)(s + adoff +  0) = pa[0];
            *(uint4*)(s + adoff + 16) = pa[1];
            *(uint4*)(s + adoff + 32) = pa[2];
            *(uint4*)(s + adoff + 48) = pa[3];
            uint32_t bo = (uint32_t)bn * PITCH + kg * 16;
            *(uint4*)(s + G2_BH + bo) = make_uint4(phi(vb[0].x, vb[0].y), phi(vb[1].x, vb[1].y),
                                                   phi(vb[2].x, vb[2].y), phi(vb[3].x, vb[3].y));
            *(uint4*)(s + G2_BL + bo) = make_uint4(plo(vb[0].x, vb[0].y), plo(vb[1].x, vb[1].y),
                                                   plo(vb[2].x, vb[2].y), plo(vb[3].x, vb[3].y));
        }
        __syncthreads();
    }

    // epilogue: accumulate into g_outrep, scatter by replica
#pragma unroll
    for (int mi = 0; mi < 2; mi++) {
        int rt = m0 + mi * 16 + g;
#pragma unroll
        for (int half = 0; half < 2; half++) {
            int row = rt + half * 8;
            int repl = g_repl_map[r0 + row];
            if (repl < 0) continue;
#pragma unroll
            for (int ni = 0; ni < 4; ni++) {
                int cb = n0 + n0w + ni * 8 + q * 2;
                float* p = g_outrep + (size_t)repl * D_DIM + cb;
                float2 v;
                v.x = c[mi][ni][half * 2 + 0];
                v.y = c[mi][ni][half * 2 + 1];
                if (!first) {
                    float2 old = *(const float2*)p;
                    v.x += old.x; v.y += old.y;
                }
                *(float2*)p = v;
            }
        }
    }
}

// ---------------- combine ----------------
__global__ void k_combine(float* __restrict__ out) {
    int i = blockIdx.x * blockDim.x + threadIdx.x;
    int t = i >> 9;
    int c = (i & 511) * 4;
    if (t >= T_TOK) return;
    float w0 = g_tw[2 * t], w1 = g_tw[2 * t + 1];
    float4 a = *(const float4*)&g_outrep[(size_t)(2 * t) * D_DIM + c];
    float4 b = *(const float4*)&g_outrep[(size_t)(2 * t + 1) * D_DIM + c];
    float4 o;
    o.x = w0 * a.x + w1 * b.x;
    o.y = w0 * a.y + w1 * b.y;
    o.z = w0 * a.z + w1 * b.z;
    o.w = w0 * a.w + w1 * b.w;
    *(float4*)&out[(size_t)t * D_DIM + c] = o;
}

// ---------------- launch ----------------
extern "C" void kernel_launch(void* const* d_in, const int* in_sizes, int n_in,
                              void* d_out, int out_size) {
    const float* x  = (const float*)d_in[0];
    const float* gw = (const float*)d_in[1];
    const float* w1 = (const float*)d_in[2];
    const float* w2 = (const float*)d_in[3];
    const float* w3 = (const float*)d_in[4];
    float* out = (float*)d_out;

    static int configured = 0;
    if (!configured) {
        cudaFuncSetAttribute(k_gemm1, cudaFuncAttributeMaxDynamicSharedMemorySize, SMEM_TOTAL);
        cudaFuncSetAttribute(k_gemm2, cudaFuncAttributeMaxDynamicSharedMemorySize, SMEM_TOTAL);
        configured = 1;
    }

    k_init<<<1, 256>>>();
    k_router<<<T_TOK / 8, 256>>>(x, gw);
    k_perm<<<1, 256>>>();
    k_xsplit<<<(T_TOK * D_DIM + 255) / 256, 256>>>(x);
    for (int c = 0; c < N_CHUNKS; c++) {
        int c0 = c * CHUNK_M;
        k_gemm1<<<dim3(MAX_RT, CHUNK_M / 32), 256, SMEM_TOTAL>>>(w1, w3, c0);
        k_gemm2<<<dim3(MAX_RT, D_DIM / 64), 256, SMEM_TOTAL>>>(w2, c0, c == 0);
    }
    k_combine<<<(T_TOK * D_DIM / 4) / 256, 256>>>(out);
}

// round 17
// speedup vs baseline: 1.3327x; 1.3327x over previous
#include <cuda_runtime.h>
#include <cuda_bf16.h>
#include <stdint.h>
#include <math.h>

// ---------------- problem constants ----------------
#define D_DIM 2048
#define M_DIM 7168
#define E_NUM 8
#define T_TOK 4096
#define TR    (T_TOK * 2)

#define TILE_M 128
#define CHUNK_M 1792
#define N_CHUNKS (M_DIM / CHUNK_M)          // 4
#define PADROWS  (TR + E_NUM * TILE_M)      // 9216
#define MAX_RT   80

#define BK 32
#define PITCH 80                            // smem row pitch = 20 banks (conflict-free frag loads)

// per-stage smem layout (bytes)
#define OFF_AH 0
#define OFF_AL 10240
#define G1_B1H 20480
#define G1_B1L 23040
#define G1_B3H 25600
#define G1_B3L 28160
#define G2_BH  20480
#define G2_BL  25600
#define STG_BYTES 30720
#define SMEM_TOTAL (2 * STG_BYTES)          // 61440

// ---------------- static device scratch (~167 MB total — proven-safe size) ----------------
__device__ __nv_bfloat16 g_xs[(size_t)T_TOK * 2 * D_DIM];       // x split [tok][part][k]
__device__ __nv_bfloat16 g_hcs[(size_t)PADROWS * 2 * CHUNK_M];  // h split [row][part][k]
__device__ float g_outrep[(size_t)TR * D_DIM];
__device__ int   g_row_map[PADROWS];
__device__ int   g_repl_map[PADROWS];
__device__ int   g_eidx[TR];
__device__ float g_tw[TR];
__device__ int   g_tile_e[MAX_RT];
__device__ int   g_tile_row[MAX_RT];
__device__ int   g_ntiles;

// ---------------- helpers ----------------
__device__ __forceinline__ uint32_t phi(float a, float b) {
    __nv_bfloat162 t = __floats2bfloat162_rn(a, b);
    return *reinterpret_cast<uint32_t*>(&t);
}
__device__ __forceinline__ uint32_t plo(float a, float b) {
    float ah = __bfloat162float(__float2bfloat16_rn(a));
    float bh = __bfloat162float(__float2bfloat16_rn(b));
    return phi(a - ah, b - bh);
}
__device__ __forceinline__ void mma16816(float* c, const uint32_t* a, const uint32_t* b) {
    asm volatile(
        "mma.sync.aligned.m16n8k16.row.col.f32.bf16.bf16.f32 "
        "{%0,%1,%2,%3}, {%4,%5,%6,%7}, {%8,%9}, {%0,%1,%2,%3};"
        : "+f"(c[0]), "+f"(c[1]), "+f"(c[2]), "+f"(c[3])
        : "r"(a[0]), "r"(a[1]), "r"(a[2]), "r"(a[3]), "r"(b[0]), "r"(b[1]));
}
__device__ __forceinline__ uint32_t lds32(const char* p) {
    return *reinterpret_cast<const uint32_t*>(p);
}
__device__ __forceinline__ float silu(float v) {
    return v / (1.f + __expf(-v));
}

// ---------------- init ----------------
__global__ void k_init() {
    for (int i = threadIdx.x; i < PADROWS; i += blockDim.x) {
        g_row_map[i]  = -1;
        g_repl_map[i] = -1;
    }
}

// ---------------- x split ----------------
__global__ void k_xsplit(const float* __restrict__ x) {
    size_t i = (size_t)blockIdx.x * blockDim.x + threadIdx.x;
    if (i >= (size_t)T_TOK * D_DIM) return;
    int tok = (int)(i / D_DIM), k = (int)(i % D_DIM);
    float v = x[i];
    __nv_bfloat16 h = __float2bfloat16_rn(v);
    g_xs[((size_t)tok * 2) * D_DIM + k] = h;
    g_xs[((size_t)tok * 2 + 1) * D_DIM + k] = __float2bfloat16_rn(v - __bfloat162float(h));
}

// ---------------- router ----------------
__global__ void k_router(const float* __restrict__ x, const float* __restrict__ gw) {
    int warp = (blockIdx.x * blockDim.x + threadIdx.x) >> 5;
    int lane = threadIdx.x & 31;
    if (warp >= T_TOK) return;
    const float* xr = x + (size_t)warp * D_DIM;
    float acc[8] = {0.f,0.f,0.f,0.f,0.f,0.f,0.f,0.f};
    for (int k = lane; k < D_DIM; k += 32) {
        float xv = xr[k];
        const float4* g4 = (const float4*)(gw + (size_t)k * E_NUM);
        float4 g0 = g4[0], g1 = g4[1];
        acc[0] += xv * g0.x; acc[1] += xv * g0.y; acc[2] += xv * g0.z; acc[3] += xv * g0.w;
        acc[4] += xv * g1.x; acc[5] += xv * g1.y; acc[6] += xv * g1.z; acc[7] += xv * g1.w;
    }
#pragma unroll
    for (int e = 0; e < 8; e++)
#pragma unroll
        for (int o = 16; o > 0; o >>= 1)
            acc[e] += __shfl_xor_sync(0xFFFFFFFFu, acc[e], o);
    if (lane == 0) {
        int e0 = 0; float l0 = acc[0];
#pragma unroll
        for (int e = 1; e < 8; e++) if (acc[e] > l0) { l0 = acc[e]; e0 = e; }
        int e1 = -1; float l1 = -3.4e38f;
#pragma unroll
        for (int e = 0; e < 8; e++) if (e != e0 && acc[e] > l1) { l1 = acc[e]; e1 = e; }
        float w0 = 1.f / (1.f + __expf(l1 - l0));
        g_eidx[2 * warp] = e0; g_eidx[2 * warp + 1] = e1;
        g_tw[2 * warp] = w0;   g_tw[2 * warp + 1] = 1.f - w0;
    }
}

// ---------------- permutation + tile list ----------------
__global__ void k_perm() {
    __shared__ int sc[E_NUM], soff[E_NUM], scur[E_NUM];
    int t = threadIdx.x;
    if (t < E_NUM) { sc[t] = 0; scur[t] = 0; }
    __syncthreads();
    for (int r = t; r < TR; r += blockDim.x) atomicAdd(&sc[g_eidx[r]], 1);
    __syncthreads();
    if (t == 0) {
        int off = 0, nt = 0;
        for (int e = 0; e < E_NUM; e++) {
            soff[e] = off;
            int cnt = sc[e];
            for (int t0 = 0; t0 < cnt; t0 += TILE_M) {
                g_tile_e[nt] = e; g_tile_row[nt] = off + t0; nt++;
            }
            off += ((cnt + TILE_M - 1) / TILE_M) * TILE_M;
        }
        g_ntiles = nt;
    }
    __syncthreads();
    for (int r = t; r < TR; r += blockDim.x) {
        int e = g_eidx[r];
        int pos = soff[e] + atomicAdd(&scur[e], 1);
        g_row_map[pos]  = r >> 1;
        g_repl_map[pos] = r;
    }
}

// ============ GEMM1: CTA 128m x 32n, warp 32m x 16n over W1 & W3 ============
__global__ void __launch_bounds__(256, 2)
k_gemm1(const float* __restrict__ w1, const float* __restrict__ w3, int c0) {
    extern __shared__ char smem[];
    int bx = blockIdx.x;
    if (bx >= g_ntiles) return;
    int e  = g_tile_e[bx];
    int r0 = g_tile_row[bx];
    int nl = blockIdx.y * 32;

    const float* W1 = w1 + (size_t)e * D_DIM * M_DIM + c0 + nl;
    const float* W3 = w3 + (size_t)e * D_DIM * M_DIM + c0 + nl;

    int tid = threadIdx.x;
    int w = tid >> 5, lane = tid & 31, g = lane >> 2, q = lane & 3;
    int m0 = (w & 3) * 32, n0w = (w >> 2) * 16;

    // A loader (pre-split bf16, COALESCED): q4 = 16B chunk, rpb = (row,part) base;
    // each thread covers 4 row-parts (rows rpb>>1 + 32i), same part throughout.
    int q4 = tid & 3, rpb = tid >> 2;
    int apart = rpb & 1, arow0 = rpb >> 1;
    const uint4* asrc[4];
    uint32_t adoff[4];
#pragma unroll
    for (int i = 0; i < 4; i++) {
        int row = arow0 + 32 * i;
        int gr = g_row_map[r0 + row];
        asrc[i] = (const uint4*)(g_xs +
            ((size_t)((gr >= 0 ? gr : 0) * 2 + apart)) * D_DIM) + q4;
        adoff[i] = (apart ? OFF_AL : OFF_AH) + (uint32_t)row * PITCH + q4 * 16;
    }

    // B loader (fp32 + convert, verified round-11 path)
    int bn = tid & 31, kg = tid >> 5;
    float2 vb1[2], vb3[2];

    char* buf[2] = { smem, smem + STG_BYTES };
    float c1[2][2][4] = {{{0}}}, c3[2][2][4] = {{{0}}};

    uint4 pa[4];
#pragma unroll
    for (int i = 0; i < 4; i++) pa[i] = asrc[i][0];
#pragma unroll
    for (int j = 0; j < 2; j++) {
        int kk = (kg * 2 + j) * 2;
        vb1[j] = make_float2(W1[(size_t)kk * M_DIM + bn], W1[(size_t)(kk + 1) * M_DIM + bn]);
        vb3[j] = make_float2(W3[(size_t)kk * M_DIM + bn], W3[(size_t)(kk + 1) * M_DIM + bn]);
    }
    {
        char* s = buf[0];
#pragma unroll
        for (int i = 0; i < 4; i++) *(uint4*)(s + adoff[i]) = pa[i];
        uint32_t bo = (uint32_t)bn * PITCH + kg * 8;
        *(uint2*)(s + G1_B1H + bo) = make_uint2(phi(vb1[0].x, vb1[0].y), phi(vb1[1].x, vb1[1].y));
        *(uint2*)(s + G1_B1L + bo) = make_uint2(plo(vb1[0].x, vb1[0].y), plo(vb1[1].x, vb1[1].y));
        *(uint2*)(s + G1_B3H + bo) = make_uint2(phi(vb3[0].x, vb3[0].y), phi(vb3[1].x, vb3[1].y));
        *(uint2*)(s + G1_B3L + bo) = make_uint2(plo(vb3[0].x, vb3[0].y), plo(vb3[1].x, vb3[1].y));
    }
    __syncthreads();

    const int NIT = D_DIM / BK;   // 64
    for (int it = 0; it < NIT; it++) {
        bool pf = (it + 1 < NIT);
        if (pf) {
            int su = (it + 1) * 4;   // uint4 stride per stage = 4
#pragma unroll
            for (int i = 0; i < 4; i++) pa[i] = asrc[i][su];
            int nk0 = (it + 1) * BK;
#pragma unroll
            for (int j = 0; j < 2; j++) {
                int kk = nk0 + (kg * 2 + j) * 2;
                vb1[j] = make_float2(W1[(size_t)kk * M_DIM + bn], W1[(size_t)(kk + 1) * M_DIM + bn]);
                vb3[j] = make_float2(W3[(size_t)kk * M_DIM + bn], W3[(size_t)(kk + 1) * M_DIM + bn]);
            }
        }
        {
            const char* s = buf[it & 1];
#pragma unroll
            for (int ks = 0; ks < 2; ks++) {
                uint32_t aH[2][4], aL[2][4];
#pragma unroll
                for (int mi = 0; mi < 2; mi++) {
                    uint32_t o = (uint32_t)(m0 + mi * 16 + g) * PITCH + ks * 32 + q * 4;
                    aH[mi][0] = lds32(s + OFF_AH + o);
                    aH[mi][1] = lds32(s + OFF_AH + o + 8 * PITCH);
                    aH[mi][2] = lds32(s + OFF_AH + o + 16);
                    aH[mi][3] = lds32(s + OFF_AH + o + 8 * PITCH + 16);
                    aL[mi][0] = lds32(s + OFF_AL + o);
                    aL[mi][1] = lds32(s + OFF_AL + o + 8 * PITCH);
                    aL[mi][2] = lds32(s + OFF_AL + o + 16);
                    aL[mi][3] = lds32(s + OFF_AL + o + 8 * PITCH + 16);
                }
                uint32_t bh[2][2], bl[2][2];
#pragma unroll
                for (int ni = 0; ni < 2; ni++) {
                    uint32_t o = (uint32_t)(n0w + ni * 8 + g) * PITCH + ks * 32 + q * 4;
                    bh[ni][0] = lds32(s + G1_B1H + o);
                    bh[ni][1] = lds32(s + G1_B1H + o + 16);
                    bl[ni][0] = lds32(s + G1_B1L + o);
                    bl[ni][1] = lds32(s + G1_B1L + o + 16);
                }
#pragma unroll
                for (int mi = 0; mi < 2; mi++)
#pragma unroll
                    for (int ni = 0; ni < 2; ni++) {
                        mma16816(c1[mi][ni], aH[mi], bh[ni]);
                        mma16816(c1[mi][ni], aL[mi], bh[ni]);
                        mma16816(c1[mi][ni], aH[mi], bl[ni]);
                    }
#pragma unroll
                for (int ni = 0; ni < 2; ni++) {
                    uint32_t o = (uint32_t)(n0w + ni * 8 + g) * PITCH + ks * 32 + q * 4;
                    bh[ni][0] = lds32(s + G1_B3H + o);
                    bh[ni][1] = lds32(s + G1_B3H + o + 16);
                    bl[ni][0] = lds32(s + G1_B3L + o);
                    bl[ni][1] = lds32(s + G1_B3L + o + 16);
                }
#pragma unroll
                for (int mi = 0; mi < 2; mi++)
#pragma unroll
                    for (int ni = 0; ni < 2; ni++) {
                        mma16816(c3[mi][ni], aH[mi], bh[ni]);
                        mma16816(c3[mi][ni], aL[mi], bh[ni]);
                        mma16816(c3[mi][ni], aH[mi], bl[ni]);
                    }
            }
        }
        if (pf) {
            char* s = buf[(it + 1) & 1];
#pragma unroll
            for (int i = 0; i < 4; i++) *(uint4*)(s + adoff[i]) = pa[i];
            uint32_t bo = (uint32_t)bn * PITCH + kg * 8;
            *(uint2*)(s + G1_B1H + bo) = make_uint2(phi(vb1[0].x, vb1[0].y), phi(vb1[1].x, vb1[1].y));
            *(uint2*)(s + G1_B1L + bo) = make_uint2(plo(vb1[0].x, vb1[0].y), plo(vb1[1].x, vb1[1].y));
            *(uint2*)(s + G1_B3H + bo) = make_uint2(phi(vb3[0].x, vb3[0].y), phi(vb3[1].x, vb3[1].y));
            *(uint2*)(s + G1_B3L + bo) = make_uint2(plo(vb3[0].x, vb3[0].y), plo(vb3[1].x, vb3[1].y));
        }
        __syncthreads();
    }

    // epilogue: h split bf16 -> g_hcs
#pragma unroll
    for (int mi = 0; mi < 2; mi++)
#pragma unroll
        for (int ni = 0; ni < 2; ni++) {
            int rt = m0 + mi * 16 + g;
            int cb = nl + n0w + ni * 8 + q * 2;
            float h0 = silu(c1[mi][ni][0]) * c3[mi][ni][0];
            float h1 = silu(c1[mi][ni][1]) * c3[mi][ni][1];
            size_t b0 = ((size_t)(r0 + rt) * 2) * CHUNK_M + cb;
            *(uint32_t*)&g_hcs[b0]           = phi(h0, h1);
            *(uint32_t*)&g_hcs[b0 + CHUNK_M] = plo(h0, h1);
            float h2 = silu(c1[mi][ni][2]) * c3[mi][ni][2];
            float h3 = silu(c1[mi][ni][3]) * c3[mi][ni][3];
            size_t b1 = ((size_t)(r0 + rt + 8) * 2) * CHUNK_M + cb;
            *(uint32_t*)&g_hcs[b1]           = phi(h2, h3);
            *(uint32_t*)&g_hcs[b1 + CHUNK_M] = plo(h2, h3);
        }
}

// ============ GEMM2: CTA 128m x 64n, warp 32m x 32n ============
__global__ void __launch_bounds__(256, 2)
k_gemm2(const float* __restrict__ w2, int c0, int first) {
    extern __shared__ char smem[];
    int bx = blockIdx.x;
    if (bx >= g_ntiles) return;
    int e  = g_tile_e[bx];
    int r0 = g_tile_row[bx];
    int n0 = blockIdx.y * 64;

    const float* W2 = w2 + (size_t)e * M_DIM * D_DIM + (size_t)c0 * D_DIM + n0;

    int tid = threadIdx.x;
    int w = tid >> 5, lane = tid & 31, g = lane >> 2, q = lane & 3;
    int m0 = (w & 3) * 32, n0w = (w >> 2) * 32;

    // A loader (pre-split bf16 h, COALESCED)
    int q4 = tid & 3, rpb = tid >> 2;
    int apart = rpb & 1, arow0 = rpb >> 1;
    const uint4* asrc[4];
    uint32_t adoff[4];
#pragma unroll
    for (int i = 0; i < 4; i++) {
        int row = arow0 + 32 * i;
        asrc[i] = (const uint4*)(g_hcs +
            ((size_t)(r0 + row) * 2 + apart) * CHUNK_M) + q4;
        adoff[i] = (apart ? OFF_AL : OFF_AH) + (uint32_t)row * PITCH + q4 * 16;
    }

    // B loader (fp32 + convert, verified round-11 path)
    int bn = tid & 63, kg = tid >> 6;
    float2 vb[4];

    char* buf[2] = { smem, smem + STG_BYTES };
    float c[2][4][4] = {{{0}}};

    uint4 pa[4];
#pragma unroll
    for (int i = 0; i < 4; i++) pa[i] = asrc[i][0];
#pragma unroll
    for (int j = 0; j < 4; j++) {
        int kk = (kg * 4 + j) * 2;
        vb[j] = make_float2(W2[(size_t)kk * D_DIM + bn], W2[(size_t)(kk + 1) * D_DIM + bn]);
    }
    {
        char* s = buf[0];
#pragma unroll
        for (int i = 0; i < 4; i++) *(uint4*)(s + adoff[i]) = pa[i];
        uint32_t bo = (uint32_t)bn * PITCH + kg * 16;
        *(uint4*)(s + G2_BH + bo) = make_uint4(phi(vb[0].x, vb[0].y), phi(vb[1].x, vb[1].y),
                                               phi(vb[2].x, vb[2].y), phi(vb[3].x, vb[3].y));
        *(uint4*)(s + G2_BL + bo) = make_uint4(plo(vb[0].x, vb[0].y), plo(vb[1].x, vb[1].y),
                                               plo(vb[2].x, vb[2].y), plo(vb[3].x, vb[3].y));
    }
    __syncthreads();

    const int NIT = CHUNK_M / BK;  // 56
    for (int it = 0; it < NIT; it++) {
        bool pf = (it + 1 < NIT);
        if (pf) {
            int su = (it + 1) * 4;
#pragma unroll
            for (int i = 0; i < 4; i++) pa[i] = asrc[i][su];
            int nk0 = (it + 1) * BK;
#pragma unroll
            for (int j = 0; j < 4; j++) {
                int kk = nk0 + (kg * 4 + j) * 2;
                vb[j] = make_float2(W2[(size_t)kk * D_DIM + bn], W2[(size_t)(kk + 1) * D_DIM + bn]);
            }
        }
        {
            const char* s = buf[it & 1];
#pragma unroll
            for (int ks = 0; ks < 2; ks++) {
                uint32_t aH[2][4], aL[2][4];
#pragma unroll
                for (int mi = 0; mi < 2; mi++) {
                    uint32_t o = (uint32_t)(m0 + mi * 16 + g) * PITCH + ks * 32 + q * 4;
                    aH[mi][0] = lds32(s + OFF_AH + o);
                    aH[mi][1] = lds32(s + OFF_AH + o + 8 * PITCH);
                    aH[mi][2] = lds32(s + OFF_AH + o + 16);
                    aH[mi][3] = lds32(s + OFF_AH + o + 8 * PITCH + 16);
                    aL[mi][0] = lds32(s + OFF_AL + o);
                    aL[mi][1] = lds32(s + OFF_AL + o + 8 * PITCH);
                    aL[mi][2] = lds32(s + OFF_AL + o + 16);
                    aL[mi][3] = lds32(s + OFF_AL + o + 8 * PITCH + 16);
                }
#pragma unroll
                for (int ni = 0; ni < 4; ni++) {
                    uint32_t o = (uint32_t)(n0w + ni * 8 + g) * PITCH + ks * 32 + q * 4;
                    uint32_t bHf[2], bLf[2];
                    bHf[0] = lds32(s + G2_BH + o);
                    bHf[1] = lds32(s + G2_BH + o + 16);
                    bLf[0] = lds32(s + G2_BL + o);
                    bLf[1] = lds32(s + G2_BL + o + 16);
#pragma unroll
                    for (int mi = 0; mi < 2; mi++) {
                        mma16816(c[mi][ni], aH[mi], bHf);
                        mma16816(c[mi][ni], aL[mi], bHf);
                        mma16816(c[mi][ni], aH[mi], bLf);
                    }
                }
            }
        }
        if (pf) {
            char* s = buf[(it + 1) & 1];
#pragma unroll
            for (int i = 0; i < 4; i++) *(uint4*)(s + adoff[i]) = pa[i];
            uint32_t bo = (uint32_t)bn * PITCH + kg * 16;
            *(uint4*)(s + G2_BH + bo) = make_uint4(phi(vb[0].x, vb[0].y), phi(vb[1].x, vb[1].y),
                                                   phi(vb[2].x, vb[2].y), phi(vb[3].x, vb[3].y));
            *(uint4*)(s + G2_BL + bo) = make_uint4(plo(vb[0].x, vb[0].y), plo(vb[1].x, vb[1].y),
                                                   plo(vb[2].x, vb[2].y), plo(vb[3].x, vb[3].y));
        }
        __syncthreads();
    }

    // epilogue: accumulate into g_outrep, scatter by replica
#pragma unroll
    for (int mi = 0; mi < 2; mi++) {
        int rt = m0 + mi * 16 + g;
#pragma unroll
        for (int half = 0; half < 2; half++) {
            int row = rt + half * 8;
            int repl = g_repl_map[r0 + row];
            if (repl < 0) continue;
#pragma unroll
            for (int ni = 0; ni < 4; ni++) {
                int cb = n0 + n0w + ni * 8 + q * 2;
                float* p = g_outrep + (size_t)repl * D_DIM + cb;
                float2 v;
                v.x = c[mi][ni][half * 2 + 0];
                v.y = c[mi][ni][half * 2 + 1];
                if (!first) {
                    float2 old = *(const float2*)p;
                    v.x += old.x; v.y += old.y;
                }
                *(float2*)p = v;
            }
        }
    }
}

// ---------------- combine ----------------
__global__ void k_combine(float* __restrict__ out) {
    int i = blockIdx.x * blockDim.x + threadIdx.x;
    int t = i >> 9;
    int c = (i & 511) * 4;
    if (t >= T_TOK) return;
    float w0 = g_tw[2 * t], w1 = g_tw[2 * t + 1];
    float4 a = *(const float4*)&g_outrep[(size_t)(2 * t) * D_DIM + c];
    float4 b = *(const float4*)&g_outrep[(size_t)(2 * t + 1) * D_DIM + c];
    float4 o;
    o.x = w0 * a.x + w1 * b.x;
    o.y = w0 * a.y + w1 * b.y;
    o.z = w0 * a.z + w1 * b.z;
    o.w = w0 * a.w + w1 * b.w;
    *(float4*)&out[(size_t)t * D_DIM + c] = o;
}

// ---------------- launch ----------------
extern "C" void kernel_launch(void* const* d_in, const int* in_sizes, int n_in,
                              void* d_out, int out_size) {
    const float* x  = (const float*)d_in[0];
    const float* gw = (const float*)d_in[1];
    const float* w1 = (const float*)d_in[2];
    const float* w2 = (const float*)d_in[3];
    const float* w3 = (const float*)d_in[4];
    float* out = (float*)d_out;

    static int configured = 0;
    if (!configured) {
        cudaFuncSetAttribute(k_gemm1, cudaFuncAttributeMaxDynamicSharedMemorySize, SMEM_TOTAL);
        cudaFuncSetAttribute(k_gemm2, cudaFuncAttributeMaxDynamicSharedMemorySize, SMEM_TOTAL);
        configured = 1;
    }

    k_init<<<1, 256>>>();
    k_router<<<T_TOK / 8, 256>>>(x, gw);
    k_perm<<<1, 256>>>();
    k_xsplit<<<(T_TOK * D_DIM + 255) / 256, 256>>>(x);
    for (int c = 0; c < N_CHUNKS; c++) {
        int c0 = c * CHUNK_M;
        k_gemm1<<<dim3(MAX_RT, CHUNK_M / 32), 256, SMEM_TOTAL>>>(w1, w3, c0);
        k_gemm2<<<dim3(MAX_RT, D_DIM / 64), 256, SMEM_TOTAL>>>(w2, c0, c == 0);
    }
    k_combine<<<(T_TOK * D_DIM / 4) / 256, 256>>>(out);
}